// round 2
// baseline (speedup 1.0000x reference)
#include <cuda_runtime.h>
#include <cuda_bf16.h>

// ConvKB scoring:
//   x = [h[row], h[col], g[type]]               [E,3,D]
//   y = relu(einsum('ekd,ck->ecd', x, conv_w) + conv_b)   [E,C,D]
//   score[e] = sum_{c,d} y[e,c,d] * lin_w[c*D+d] + lin_b
//
// E=50000, D=128, C=32. Warp-per-edge, lane owns 4 consecutive d (float4).
// NOTE: edge_idx / edge_type are int32 (JAX x64-disabled truncates int64).

#define D 128
#define C 32
#define WARPS_PER_BLOCK 8
#define THREADS (WARPS_PER_BLOCK * 32)
#define NBLOCKS 888   // 6 blocks/SM on 148 SMs

__global__ void __launch_bounds__(THREADS) convkb_kernel(
    const float* __restrict__ h,
    const float* __restrict__ g,
    const int*   __restrict__ edge_idx,   // [2, E] int32
    const int*   __restrict__ edge_type,  // [E]    int32
    const float* __restrict__ conv_w,     // [C,3]
    const float* __restrict__ conv_b,     // [C]
    const float* __restrict__ lin_w,      // [C*D]
    const float* __restrict__ lin_b,      // [1]
    float* __restrict__ out,              // [E]
    int n_edges)
{
    __shared__ float4 s_lin[C * D / 4];   // 4096 floats = 16 KB
    __shared__ float4 s_conv[C];          // {w0, w1, w2, bias} per channel

    const int tid = threadIdx.x;

    // Stage lin_w into shared (vectorized)
    const float4* lw4 = reinterpret_cast<const float4*>(lin_w);
    #pragma unroll 4
    for (int i = tid; i < C * D / 4; i += THREADS) s_lin[i] = lw4[i];
    if (tid < C) {
        s_conv[tid] = make_float4(conv_w[tid * 3 + 0],
                                  conv_w[tid * 3 + 1],
                                  conv_w[tid * 3 + 2],
                                  conv_b[tid]);
    }
    __syncthreads();

    const float bias_out = lin_b[0];

    const int warp = tid >> 5;
    const int lane = tid & 31;
    const int warp_global = blockIdx.x * WARPS_PER_BLOCK + warp;
    const int n_warps = gridDim.x * WARPS_PER_BLOCK;

    for (int e = warp_global; e < n_edges; e += n_warps) {
        const int row = edge_idx[e];
        const int col = edge_idx[n_edges + e];
        const int t   = edge_type[e];

        // Each lane loads its 4 d-values of head/tail/relation embeddings.
        // 512B-aligned, fully coalesced across the warp. h fits in L2 (25.6MB).
        const float4 a = __ldg(reinterpret_cast<const float4*>(h + (long long)row * D) + lane);
        const float4 b = __ldg(reinterpret_cast<const float4*>(h + (long long)col * D) + lane);
        const float4 r = __ldg(reinterpret_cast<const float4*>(g + (long long)t   * D) + lane);

        float acc = 0.0f;

        #pragma unroll
        for (int c = 0; c < C; c++) {
            const float4 w  = s_conv[c];                 // broadcast LDS.128
            const float4 lw = s_lin[c * (D / 4) + lane]; // conflict-free LDS.128

            float y0 = fmaf(w.x, a.x, fmaf(w.y, b.x, fmaf(w.z, r.x, w.w)));
            float y1 = fmaf(w.x, a.y, fmaf(w.y, b.y, fmaf(w.z, r.y, w.w)));
            float y2 = fmaf(w.x, a.z, fmaf(w.y, b.z, fmaf(w.z, r.z, w.w)));
            float y3 = fmaf(w.x, a.w, fmaf(w.y, b.w, fmaf(w.z, r.w, w.w)));

            y0 = fmaxf(y0, 0.0f);
            y1 = fmaxf(y1, 0.0f);
            y2 = fmaxf(y2, 0.0f);
            y3 = fmaxf(y3, 0.0f);

            acc = fmaf(y0, lw.x, acc);
            acc = fmaf(y1, lw.y, acc);
            acc = fmaf(y2, lw.z, acc);
            acc = fmaf(y3, lw.w, acc);
        }

        // Warp reduction over lanes (each lane covered 4 d's, all c's)
        #pragma unroll
        for (int o = 16; o > 0; o >>= 1)
            acc += __shfl_xor_sync(0xFFFFFFFFu, acc, o);

        if (lane == 0) out[e] = acc + bias_out;
    }
}

extern "C" void kernel_launch(void* const* d_in, const int* in_sizes, int n_in,
                              void* d_out, int out_size) {
    const float* h         = (const float*)d_in[0];
    const float* g         = (const float*)d_in[1];
    const int*   edge_idx  = (const int*)d_in[2];
    const int*   edge_type = (const int*)d_in[3];
    const float* conv_w    = (const float*)d_in[4];
    const float* conv_b    = (const float*)d_in[5];
    const float* lin_w     = (const float*)d_in[6];
    const float* lin_b     = (const float*)d_in[7];
    float*       out       = (float*)d_out;

    const int n_edges = in_sizes[3];  // edge_type element count == E

    int nblocks = NBLOCKS;
    int max_needed = (n_edges + WARPS_PER_BLOCK - 1) / WARPS_PER_BLOCK;
    if (nblocks > max_needed) nblocks = max_needed;

    convkb_kernel<<<nblocks, THREADS>>>(h, g, edge_idx, edge_type,
                                        conv_w, conv_b, lin_w, lin_b,
                                        out, n_edges);
}